// round 12
// baseline (speedup 1.0000x reference)
#include <cuda_runtime.h>
#include <cuda_fp16.h>
#include <math.h>
#include <stdint.h>

#define BATCH 8192
#define U2    2048
#define GL    6144

#define BM 128
#define BN 128
#define BK 64
#define STAGES 3
#define THREADS 256

#define A_STAGE_BYTES (BM * BK * 2)            // 16384: 128 rows x 128B, SW128
#define BROWB 272                               // B smem row bytes (256 data + 16 pad)
#define B_STAGE_BYTES (BK * BROWB)              // 17408
#define STAGE_BYTES (A_STAGE_BYTES + B_STAGE_BYTES)   // 33792
#define SMEM_ALLOC (STAGES * STAGE_BYTES + 256)       // ~99.3 KB -> 2 CTAs/SM

#define NT_A 3072      // A tiles: 64 m-blocks x 48 n-tiles (m-major)
#define NTOT 4096      // + 1024 B tiles: 64 m-blocks x 16 n-tiles

// fp16 operand copies + intermediates (allocation-free scratch)
__device__ __half g_xH [(size_t)BATCH * U2];
__device__ __half g_hH [(size_t)BATCH * U2];
__device__ __half g_WinH[(size_t)U2 * GL];
__device__ __half g_WhH [(size_t)U2 * GL];
__device__ __half g_rhH[(size_t)BATCH * U2];   // fp16 r*h
__device__ float  g_U  [(size_t)BATCH * U2];   // update gate (fp32)
__device__ float  g_XH [(size_t)BATCH * U2];   // x@Win[:,2u:] (fp32)

// scheduling state (reset each launch inside cvt kernel)
__device__ unsigned g_work;
__device__ unsigned g_done[64];

// ---------------- helpers ----------------
__device__ __forceinline__ uint32_t smem_u32(const void* p) {
    uint32_t a;
    asm("{ .reg .u64 t; cvta.to.shared.u64 t, %1; cvt.u32.u64 %0, t; }" : "=r"(a) : "l"(p));
    return a;
}
__device__ __forceinline__ void cp16(uint32_t dst, const void* src) {
    asm volatile("cp.async.cg.shared.global [%0], [%1], 16;" :: "r"(dst), "l"(src));
}
__device__ __forceinline__ void cp_commit() {
    asm volatile("cp.async.commit_group;" ::: "memory");
}
template<int N> __device__ __forceinline__ void cp_wait() {
    asm volatile("cp.async.wait_group %0;" :: "n"(N) : "memory");
}
__device__ __forceinline__ void ldsm_x4(uint32_t* r, uint32_t addr) {
    asm volatile("ldmatrix.sync.aligned.m8n8.x4.shared.b16 {%0,%1,%2,%3}, [%4];"
                 : "=r"(r[0]), "=r"(r[1]), "=r"(r[2]), "=r"(r[3]) : "r"(addr));
}
__device__ __forceinline__ void ldsm_x4_t(uint32_t* r, uint32_t addr) {
    asm volatile("ldmatrix.sync.aligned.m8n8.x4.trans.shared.b16 {%0,%1,%2,%3}, [%4];"
                 : "=r"(r[0]), "=r"(r[1]), "=r"(r[2]), "=r"(r[3]) : "r"(addr));
}
__device__ __forceinline__ void mma_f16(float* d, const uint32_t* a, const uint32_t* b) {
    asm volatile(
        "mma.sync.aligned.m16n8k16.row.col.f32.f16.f16.f32 "
        "{%0,%1,%2,%3}, {%4,%5,%6,%7}, {%8,%9}, {%0,%1,%2,%3};"
        : "+f"(d[0]), "+f"(d[1]), "+f"(d[2]), "+f"(d[3])
        : "r"(a[0]), "r"(a[1]), "r"(a[2]), "r"(a[3]), "r"(b[0]), "r"(b[1]));
}
__device__ __forceinline__ unsigned ld_acq(const unsigned* p) {
    unsigned v;
    asm volatile("ld.acquire.gpu.b32 %0, [%1];" : "=r"(v) : "l"(p) : "memory");
    return v;
}
__device__ __forceinline__ float sigmoidf_(float x) { return 1.0f / (1.0f + __expf(-x)); }

// ---------------- tile decode ----------------
struct TileInfo {
    int mblk, n0, K, region;
    const __half *a0, *a1, *b0, *b1;
};
__device__ __forceinline__ TileInfo decode_tile(int t) {
    TileInfo ti;
    if (t < NT_A) {
        ti.mblk = t / 48;
        const int nt = t % 48;
        ti.n0 = nt * 128;
        ti.K  = (nt < 32) ? 4096 : 2048;
        ti.region = ti.n0 >> 11;                 // 0=r, 1=u, 2=xh
        ti.a0 = g_xH;  ti.a1 = g_hH;
        ti.b0 = g_WinH + ti.n0;  ti.b1 = g_WhH + ti.n0;
    } else {
        const int u = t - NT_A;
        ti.mblk = u >> 4;
        ti.n0 = (u & 15) * 128;
        ti.K = 2048; ti.region = 3;
        ti.a0 = g_rhH;  ti.a1 = g_rhH;
        ti.b0 = g_WhH + 4096 + ti.n0;  ti.b1 = ti.b0;
    }
    return ti;
}

// ---------------- stage fill (256 threads, BK=64, BN=128) ----------------
__device__ __forceinline__ void fill_stage(int tid, uint32_t stA, uint32_t stB,
                                           int m0, int k0, const TileInfo& ti)
{
    // ---- A: row = tid>>1 (0..127), 4 x 16B granules each ----
    const int row = tid >> 1;
    const int c0a = (tid & 1) * 4;
#pragma unroll
    for (int j = 0; j < 4; j++) {
        const int ch = c0a + j;                  // 0..7
        const int kg = k0 + ch * 8;
        const __half* src = (kg < 2048)
            ? ti.a0 + (size_t)(m0 + row) * U2 + kg
            : ti.a1 + (size_t)(m0 + row) * U2 + (kg - 2048);
        cp16(stA + (uint32_t)(row << 7) + (uint32_t)(((ch ^ (row & 7)) << 4)), src);
    }
    // ---- B: k-row = tid>>2 (0..63), 4 x 16B granules across 128 n ----
    const int kb = tid >> 2;
    const int kg = k0 + kb;
    const __half* brow = (kg < 2048)
        ? ti.b0 + (size_t)kg * GL
        : ti.b1 + (size_t)(kg - 2048) * GL;
    const uint32_t bbase = stB + (uint32_t)(kb * BROWB) + (uint32_t)((tid & 3) << 4);
#pragma unroll
    for (int q = 0; q < 4; q++)
        cp16(bbase + (uint32_t)(q << 6), brow + (tid & 3) * 8 + q * 32);
}

// ---------------- fused persistent GRU kernel (2 CTAs/SM) ----------------
__global__ void __launch_bounds__(THREADS, 2)
gru_fused(const float* __restrict__ h_exact, const float* __restrict__ bias,
          float* __restrict__ out)
{
    extern __shared__ char smem_raw[];
    const uint32_t base = (smem_u32(smem_raw) + 127u) & ~127u;
    volatile int* sm_ints = (volatile int*)(smem_raw + STAGES * STAGE_BYTES + 128);

    const int tid  = threadIdx.x;
    const int lane = tid & 31;
    const int wid  = tid >> 5;
    const int warp_m = wid & 3;          // 32-row quarters
    const int warp_n = wid >> 2;         // 64-col halves

    // ldmatrix lane decomposition
    const int g = lane >> 3;
    const int r = lane & 7;
    const int a_mlocal = ((g & 1) << 3) + r;
    const int a_khalf  = g >> 1;
    const uint32_t a_rowoff = (uint32_t)((warp_m * 32 + a_mlocal) << 7);
    const int b_klocal = ((g & 1) << 3) + r;
    const int b_noct   = g >> 1;

    for (;;) {
        // ---- grab a tile ----
        if (tid == 0) sm_ints[0] = (int)atomicAdd(&g_work, 1u);
        __syncthreads();
        const int t = sm_ints[0];
        if (t >= NTOT) break;

        const TileInfo ti = decode_tile(t);
        if (ti.region == 3) {
            if (tid == 0) {
                while (ld_acq(&g_done[ti.mblk]) < 48u) __nanosleep(64);
            }
            __syncthreads();
        }
        const int m0 = ti.mblk * 128;
        const int NC = ti.K / BK;        // 64 or 32

        float d[2][8][4];
#pragma unroll
        for (int mf = 0; mf < 2; mf++)
#pragma unroll
            for (int nf = 0; nf < 8; nf++)
#pragma unroll
                for (int q = 0; q < 4; q++) d[mf][nf][q] = 0.0f;

        // ---- pipeline prologue: chunks 0,1 -> stages 0,1 ----
        fill_stage(tid, base, base + A_STAGE_BYTES, m0, 0, ti);
        cp_commit();
        fill_stage(tid, base + STAGE_BYTES, base + STAGE_BYTES + A_STAGE_BYTES,
                   m0, BK, ti);
        cp_commit();

        // ---- main K loop (race-free 3-stage: fill AFTER barrier) ----
        for (int c = 0; c < NC; c++) {
            cp_wait<1>();                // chunk c resident (group c+1 may fly)
            __syncthreads();             // all warps done reading chunk c-1

            if (c + 2 < NC) {
                // stage (c+2)%3 == stage of chunk c-1: safe after barrier
                const uint32_t sb = base + (uint32_t)((c + 2) % STAGES) * STAGE_BYTES;
                fill_stage(tid, sb, sb + A_STAGE_BYTES, m0, (c + 2) * BK, ti);
            }
            cp_commit();                 // empty group when no fill: keeps accounting

            const uint32_t cs  = base + (uint32_t)(c % STAGES) * STAGE_BYTES;
            const uint32_t stB = cs + A_STAGE_BYTES;

#pragma unroll
            for (int ks = 0; ks < 4; ks++) {
                uint32_t a[2][4];
#pragma unroll
                for (int mf = 0; mf < 2; mf++) {
                    const uint32_t addr = cs + a_rowoff + (uint32_t)(mf << 11)
                                        + (uint32_t)((((ks << 1) + a_khalf) ^ r) << 4);
                    ldsm_x4(a[mf], addr);
                }
                uint32_t b[8][2];
#pragma unroll
                for (int pr = 0; pr < 4; pr++) {
                    uint32_t bb[4];
                    const uint32_t addr = stB
                        + (uint32_t)((ks * 16 + b_klocal) * BROWB)
                        + (uint32_t)((warp_n * 64 + pr * 16 + b_noct * 8) << 1);
                    ldsm_x4_t(bb, addr);
                    b[pr * 2 + 0][0] = bb[0]; b[pr * 2 + 0][1] = bb[1];
                    b[pr * 2 + 1][0] = bb[2]; b[pr * 2 + 1][1] = bb[3];
                }
#pragma unroll
                for (int mf = 0; mf < 2; mf++)
#pragma unroll
                    for (int nf = 0; nf < 8; nf++)
                        mma_f16(d[mf][nf], a[mf], b[nf]);
            }
        }
        cp_wait<0>();

        // ---- epilogue ----
        const int region = ti.region;
        const int n0 = ti.n0;
#pragma unroll
        for (int mf = 0; mf < 2; mf++) {
#pragma unroll
            for (int nf = 0; nf < 8; nf++) {
                const int gc = n0 + warp_n * 64 + nf * 8 + (lane & 3) * 2;
#pragma unroll
                for (int half = 0; half < 2; half++) {
                    const int grow = m0 + warp_m * 32 + mf * 16 + (lane >> 2) + half * 8;
                    const float v0 = d[mf][nf][half * 2 + 0];
                    const float v1 = d[mf][nf][half * 2 + 1];
                    const size_t rb = (size_t)grow * U2;

                    if (region == 0) {
                        const int nl = gc;
                        float2 bv = *(const float2*)(bias + gc);
                        float2 hv = *(const float2*)(h_exact + rb + nl);
                        __half2 o = __floats2half2_rn(sigmoidf_(v0 + bv.x) * hv.x,
                                                      sigmoidf_(v1 + bv.y) * hv.y);
                        *(__half2*)(g_rhH + rb + nl) = o;
                    } else if (region == 1) {
                        const int nl = gc & 2047;
                        float2 bv = *(const float2*)(bias + gc);
                        float2 o;
                        o.x = sigmoidf_(v0 + bv.x);
                        o.y = sigmoidf_(v1 + bv.y);
                        *(float2*)(g_U + rb + nl) = o;
                    } else if (region == 2) {
                        const int nl = gc & 2047;
                        float2 o; o.x = v0; o.y = v1;
                        *(float2*)(g_XH + rb + nl) = o;
                    } else {
                        float2 xh = *(const float2*)(g_XH + rb + gc);
                        float2 uu = *(const float2*)(g_U  + rb + gc);
                        float2 hv = *(const float2*)(h_exact + rb + gc);
                        float2 bv = *(const float2*)(bias + 4096 + gc);
                        float2 o;
                        const float c0 = tanhf(v0 + xh.x + bv.x);
                        const float c1 = tanhf(v1 + xh.y + bv.y);
                        o.x = uu.x * hv.x + (1.0f - uu.x) * c0;
                        o.y = uu.y * hv.y + (1.0f - uu.y) * c1;
                        *(float2*)(out + rb + gc) = o;
                    }
                }
            }
        }

        // ---- publish completion (A tiles) ----
        __threadfence();
        __syncthreads();                 // protects sm_ints reuse as well
        if (region < 3 && tid == 0) atomicAdd(&g_done[ti.mblk], 1u);
    }
}

// ---------------- fused fp32 -> fp16 conversion + counter reset ----------------
__global__ void __launch_bounds__(256)
cvt_all_kernel(const float4* __restrict__ x, const float4* __restrict__ h,
               const float4* __restrict__ wi, const float4* __restrict__ wh)
{
    if (blockIdx.x == 0) {
        if (threadIdx.x < 64) g_done[threadIdx.x] = 0u;
        if (threadIdx.x == 64) g_work = 0u;
    }
    const int nx = BATCH * U2 / 4;
    const int nw = U2 * GL / 4;
    const int total = 2 * nx + 2 * nw;
    for (int i = blockIdx.x * blockDim.x + threadIdx.x; i < total;
         i += gridDim.x * blockDim.x) {
        const float4* src; __half2* dst; int j;
        if (i < nx)               { src = x;  dst = (__half2*)g_xH;   j = i; }
        else if (i < 2 * nx)      { src = h;  dst = (__half2*)g_hH;   j = i - nx; }
        else if (i < 2 * nx + nw) { src = wi; dst = (__half2*)g_WinH; j = i - 2 * nx; }
        else                      { src = wh; dst = (__half2*)g_WhH;  j = i - 2 * nx - nw; }
        float4 v = src[j];
        dst[2 * j + 0] = __floats2half2_rn(v.x, v.y);
        dst[2 * j + 1] = __floats2half2_rn(v.z, v.w);
    }
}

// ---------------- host ----------------
extern "C" void kernel_launch(void* const* d_in, const int* in_sizes, int n_in,
                              void* d_out, int out_size)
{
    const float* x    = (const float*)d_in[0];
    const float* h    = (const float*)d_in[1];
    const float* Win  = (const float*)d_in[2];
    const float* Wh   = (const float*)d_in[3];
    const float* bias = (const float*)d_in[4];
    float* out = (float*)d_out;

    static int nsm = 0;
    if (nsm == 0) {
        cudaDeviceGetAttribute(&nsm, cudaDevAttrMultiProcessorCount, 0);
        if (nsm <= 0) nsm = 148;
        cudaFuncSetAttribute(gru_fused, cudaFuncAttributeMaxDynamicSharedMemorySize,
                             SMEM_ALLOC);
    }

    cvt_all_kernel<<<2048, 256>>>((const float4*)x, (const float4*)h,
                                  (const float4*)Win, (const float4*)Wh);
    gru_fused<<<2 * nsm, THREADS, SMEM_ALLOC>>>(h, bias, out);
}

// round 13
// speedup vs baseline: 1.0325x; 1.0325x over previous
#include <cuda_runtime.h>
#include <cuda_fp16.h>
#include <math.h>
#include <stdint.h>

#define BATCH 8192
#define U2    2048
#define GL    6144

#define BM 128
#define BN 256
#define BK 64
#define STAGES 4
#define THREADS 512

#define A_STAGE_BYTES (BM * BK * 2)            // 16384: 128 rows x 128B, SW128
#define BROWB 528                               // B smem row bytes (512 data + 16 pad)
#define B_STAGE_BYTES (BK * BROWB)              // 33792
#define STAGE_BYTES (A_STAGE_BYTES + B_STAGE_BYTES)   // 50176
#define SMEM_ALLOC (STAGES * STAGE_BYTES + 256)

#define NT_A 1536      // A tiles: 64 m-blocks x 24 n-tiles (m-major)
#define NTOT 2048      // + 512 B tiles: 64 m-blocks x 8 n-tiles

// fp16 operand copies + intermediates (allocation-free scratch)
__device__ __half g_xH [(size_t)BATCH * U2];
__device__ __half g_hH [(size_t)BATCH * U2];
__device__ __half g_WinH[(size_t)U2 * GL];
__device__ __half g_WhH [(size_t)U2 * GL];
__device__ __half g_rhH[(size_t)BATCH * U2];   // fp16 r*h
__device__ float  g_U  [(size_t)BATCH * U2];   // update gate (fp32)
__device__ float  g_XH [(size_t)BATCH * U2];   // x@Win[:,2u:] (fp32)

// scheduling state (reset each launch inside cvt kernel)
__device__ unsigned g_work;
__device__ unsigned g_done[64];

// ---------------- helpers ----------------
__device__ __forceinline__ uint32_t smem_u32(const void* p) {
    uint32_t a;
    asm("{ .reg .u64 t; cvta.to.shared.u64 t, %1; cvt.u32.u64 %0, t; }" : "=r"(a) : "l"(p));
    return a;
}
__device__ __forceinline__ void cp16(uint32_t dst, const void* src) {
    asm volatile("cp.async.cg.shared.global [%0], [%1], 16;" :: "r"(dst), "l"(src));
}
__device__ __forceinline__ void cp_commit() {
    asm volatile("cp.async.commit_group;" ::: "memory");
}
template<int N> __device__ __forceinline__ void cp_wait() {
    asm volatile("cp.async.wait_group %0;" :: "n"(N) : "memory");
}
__device__ __forceinline__ void ldsm_x4(uint32_t* r, uint32_t addr) {
    asm volatile("ldmatrix.sync.aligned.m8n8.x4.shared.b16 {%0,%1,%2,%3}, [%4];"
                 : "=r"(r[0]), "=r"(r[1]), "=r"(r[2]), "=r"(r[3]) : "r"(addr));
}
__device__ __forceinline__ void ldsm_x4_t(uint32_t* r, uint32_t addr) {
    asm volatile("ldmatrix.sync.aligned.m8n8.x4.trans.shared.b16 {%0,%1,%2,%3}, [%4];"
                 : "=r"(r[0]), "=r"(r[1]), "=r"(r[2]), "=r"(r[3]) : "r"(addr));
}
__device__ __forceinline__ void mma_f16(float* d, const uint32_t* a, const uint32_t* b) {
    asm volatile(
        "mma.sync.aligned.m16n8k16.row.col.f32.f16.f16.f32 "
        "{%0,%1,%2,%3}, {%4,%5,%6,%7}, {%8,%9}, {%0,%1,%2,%3};"
        : "+f"(d[0]), "+f"(d[1]), "+f"(d[2]), "+f"(d[3])
        : "r"(a[0]), "r"(a[1]), "r"(a[2]), "r"(a[3]), "r"(b[0]), "r"(b[1]));
}
__device__ __forceinline__ unsigned ld_acq(const unsigned* p) {
    unsigned v;
    asm volatile("ld.acquire.gpu.b32 %0, [%1];" : "=r"(v) : "l"(p) : "memory");
    return v;
}
__device__ __forceinline__ float sigmoidf_(float x) { return 1.0f / (1.0f + __expf(-x)); }

// ---------------- tile decode ----------------
struct TileInfo {
    int mblk, n0, K, region;
    const __half *a0, *a1, *b0, *b1;
};
__device__ __forceinline__ TileInfo decode_tile(int t) {
    TileInfo ti;
    if (t < NT_A) {
        ti.mblk = t / 24;
        const int nt = t % 24;
        ti.n0 = nt * 256;
        ti.K  = (nt < 16) ? 4096 : 2048;
        ti.region = ti.n0 >> 11;                 // 0=r, 1=u, 2=xh
        ti.a0 = g_xH;  ti.a1 = g_hH;
        ti.b0 = g_WinH + ti.n0;  ti.b1 = g_WhH + ti.n0;
    } else {
        const int u = t - NT_A;
        ti.mblk = u >> 3;
        ti.n0 = (u & 7) * 256;
        ti.K = 2048; ti.region = 3;
        ti.a0 = g_rhH;  ti.a1 = g_rhH;
        ti.b0 = g_WhH + 4096 + ti.n0;  ti.b1 = ti.b0;
    }
    return ti;
}

// ---------------- stage fill (512 threads, BK=64) ----------------
__device__ __forceinline__ void fill_stage(int tid, uint32_t stA, uint32_t stB,
                                           int m0, int k0, const TileInfo& ti)
{
    // ---- A: row = tid>>2, 2 x 16B chunks each ----
    const int row = tid >> 2;
    const int c0a = (tid & 3) * 2;
#pragma unroll
    for (int j = 0; j < 2; j++) {
        const int ch = c0a + j;                  // 0..7
        const int kg = k0 + ch * 8;
        const __half* src = (kg < 2048)
            ? ti.a0 + (size_t)(m0 + row) * U2 + kg
            : ti.a1 + (size_t)(m0 + row) * U2 + (kg - 2048);
        cp16(stA + (uint32_t)(row << 7) + (uint32_t)(((ch ^ (row & 7)) << 4)), src);
    }
    // ---- B: k-row = tid>>3 (0..63), 4 x 16B chunks across 256 n ----
    const int kb = tid >> 3;
    const int kg = k0 + kb;
    const __half* brow = (kg < 2048)
        ? ti.b0 + (size_t)kg * GL
        : ti.b1 + (size_t)(kg - 2048) * GL;
    const uint32_t bbase = stB + (uint32_t)(kb * BROWB) + (uint32_t)((tid & 7) << 4);
#pragma unroll
    for (int q = 0; q < 4; q++)
        cp16(bbase + (uint32_t)(q << 7), brow + (tid & 7) * 8 + q * 64);
}

// ---------------- fused persistent GRU kernel ----------------
__global__ void __launch_bounds__(THREADS, 1)
gru_fused(const float* __restrict__ h_exact, const float* __restrict__ bias,
          float* __restrict__ out)
{
    extern __shared__ char smem_raw[];
    const uint32_t base = (smem_u32(smem_raw) + 127u) & ~127u;
    volatile int* sm_ints = (volatile int*)(smem_raw + STAGES * STAGE_BYTES + 128);

    const int tid  = threadIdx.x;
    const int lane = tid & 31;
    const int wid  = tid >> 5;
    const int warp_m = wid & 3;          // 32-row quarters
    const int warp_n = wid >> 2;         // 64-col quarters

    // ldmatrix lane decomposition
    const int g = lane >> 3;
    const int r = lane & 7;
    const int a_mlocal = ((g & 1) << 3) + r;
    const int a_khalf  = g >> 1;
    const uint32_t a_rowoff = (uint32_t)((warp_m * 32 + a_mlocal) << 7);
    const int b_klocal = ((g & 1) << 3) + r;
    const int b_noct   = g >> 1;

    for (;;) {
        // ---- grab a tile ----
        if (tid == 0) sm_ints[0] = (int)atomicAdd(&g_work, 1u);
        __syncthreads();
        const int t = sm_ints[0];
        if (t >= NTOT) break;

        const TileInfo ti = decode_tile(t);
        if (ti.region == 3) {
            if (tid == 0) {
                while (ld_acq(&g_done[ti.mblk]) < 24u) __nanosleep(64);
            }
            __syncthreads();
        }
        const int m0 = ti.mblk * 128;
        const int NC = ti.K / BK;        // 64 or 32 (multiple of 4)

        float d[2][8][4];
#pragma unroll
        for (int mf = 0; mf < 2; mf++)
#pragma unroll
            for (int nf = 0; nf < 8; nf++)
#pragma unroll
                for (int q = 0; q < 4; q++) d[mf][nf][q] = 0.0f;

        // ---- compute-one-chunk lambda (stage s) ----
        auto compute_chunk = [&](uint32_t cs) {
            const uint32_t stB = cs + A_STAGE_BYTES;
#pragma unroll
            for (int ks = 0; ks < 4; ks++) {
                uint32_t a[2][4];
#pragma unroll
                for (int mf = 0; mf < 2; mf++) {
                    const uint32_t addr = cs + a_rowoff + (uint32_t)(mf << 11)
                                        + (uint32_t)((((ks << 1) + a_khalf) ^ r) << 4);
                    ldsm_x4(a[mf], addr);
                }
                uint32_t b[8][2];
#pragma unroll
                for (int pr = 0; pr < 4; pr++) {
                    uint32_t bb[4];
                    const uint32_t addr = stB
                        + (uint32_t)((ks * 16 + b_klocal) * BROWB)
                        + (uint32_t)((warp_n * 64 + pr * 16 + b_noct * 8) << 1);
                    ldsm_x4_t(bb, addr);
                    b[pr * 2 + 0][0] = bb[0]; b[pr * 2 + 0][1] = bb[1];
                    b[pr * 2 + 1][0] = bb[2]; b[pr * 2 + 1][1] = bb[3];
                }
#pragma unroll
                for (int mf = 0; mf < 2; mf++)
#pragma unroll
                    for (int nf = 0; nf < 8; nf++)
                        mma_f16(d[mf][nf], a[mf], b[nf]);
            }
        };

        // ---- pipeline prologue: chunks 0,1 as ONE group ----
        fill_stage(tid, base, base + A_STAGE_BYTES, m0, 0, ti);
        fill_stage(tid, base + STAGE_BYTES, base + STAGE_BYTES + A_STAGE_BYTES,
                   m0, BK, ti);
        cp_commit();

        // ---- main K loop: 2 chunks per barrier ----
        for (int c = 0; c < NC; c += 2) {
            cp_wait<0>();                // pair (c,c+1) resident (committed 1 iter ago)
            __syncthreads();             // all warps done reading pair (c-2,c-1)

            if (c + 2 < NC) {
                // stages (c+2)%4,(c+3)%4 == stages of (c-2,c-1): safe after barrier
                const uint32_t s2 = base + (uint32_t)((c + 2) % STAGES) * STAGE_BYTES;
                const uint32_t s3 = base + (uint32_t)((c + 3) % STAGES) * STAGE_BYTES;
                fill_stage(tid, s2, s2 + A_STAGE_BYTES, m0, (c + 2) * BK, ti);
                fill_stage(tid, s3, s3 + A_STAGE_BYTES, m0, (c + 3) * BK, ti);
                cp_commit();             // one group per pair
            }

            compute_chunk(base + (uint32_t)(c % STAGES) * STAGE_BYTES);
            compute_chunk(base + (uint32_t)((c + 1) % STAGES) * STAGE_BYTES);
        }

        // ---- epilogue ----
        const int region = ti.region;
        const int n0 = ti.n0;
#pragma unroll
        for (int mf = 0; mf < 2; mf++) {
#pragma unroll
            for (int nf = 0; nf < 8; nf++) {
                const int gc = n0 + warp_n * 64 + nf * 8 + (lane & 3) * 2;
#pragma unroll
                for (int half = 0; half < 2; half++) {
                    const int grow = m0 + warp_m * 32 + mf * 16 + (lane >> 2) + half * 8;
                    const float v0 = d[mf][nf][half * 2 + 0];
                    const float v1 = d[mf][nf][half * 2 + 1];
                    const size_t rb = (size_t)grow * U2;

                    if (region == 0) {
                        const int nl = gc;
                        float2 bv = *(const float2*)(bias + gc);
                        float2 hv = *(const float2*)(h_exact + rb + nl);
                        __half2 o = __floats2half2_rn(sigmoidf_(v0 + bv.x) * hv.x,
                                                      sigmoidf_(v1 + bv.y) * hv.y);
                        *(__half2*)(g_rhH + rb + nl) = o;
                    } else if (region == 1) {
                        const int nl = gc & 2047;
                        float2 bv = *(const float2*)(bias + gc);
                        float2 o;
                        o.x = sigmoidf_(v0 + bv.x);
                        o.y = sigmoidf_(v1 + bv.y);
                        *(float2*)(g_U + rb + nl) = o;
                    } else if (region == 2) {
                        const int nl = gc & 2047;
                        float2 o; o.x = v0; o.y = v1;
                        *(float2*)(g_XH + rb + nl) = o;
                    } else {
                        float2 xh = *(const float2*)(g_XH + rb + gc);
                        float2 uu = *(const float2*)(g_U  + rb + gc);
                        float2 hv = *(const float2*)(h_exact + rb + gc);
                        float2 bv = *(const float2*)(bias + 4096 + gc);
                        float2 o;
                        const float c0 = tanhf(v0 + xh.x + bv.x);
                        const float c1 = tanhf(v1 + xh.y + bv.y);
                        o.x = uu.x * hv.x + (1.0f - uu.x) * c0;
                        o.y = uu.y * hv.y + (1.0f - uu.y) * c1;
                        *(float2*)(out + rb + gc) = o;
                    }
                }
            }
        }

        // ---- publish completion (A tiles) ----
        __threadfence();
        __syncthreads();                 // protects sm_ints reuse as well
        if (region < 3 && tid == 0) atomicAdd(&g_done[ti.mblk], 1u);
    }
}

// ---------------- fused fp32 -> fp16 conversion + counter reset ----------------
__global__ void __launch_bounds__(256)
cvt_all_kernel(const float4* __restrict__ x, const float4* __restrict__ h,
               const float4* __restrict__ wi, const float4* __restrict__ wh)
{
    if (blockIdx.x == 0) {
        if (threadIdx.x < 64) g_done[threadIdx.x] = 0u;
        if (threadIdx.x == 64) g_work = 0u;
    }
    const int nx = BATCH * U2 / 4;
    const int nw = U2 * GL / 4;
    const int total = 2 * nx + 2 * nw;
    for (int i = blockIdx.x * blockDim.x + threadIdx.x; i < total;
         i += gridDim.x * blockDim.x) {
        const float4* src; __half2* dst; int j;
        if (i < nx)               { src = x;  dst = (__half2*)g_xH;   j = i; }
        else if (i < 2 * nx)      { src = h;  dst = (__half2*)g_hH;   j = i - nx; }
        else if (i < 2 * nx + nw) { src = wi; dst = (__half2*)g_WinH; j = i - 2 * nx; }
        else                      { src = wh; dst = (__half2*)g_WhH;  j = i - 2 * nx - nw; }
        float4 v = src[j];
        dst[2 * j + 0] = __floats2half2_rn(v.x, v.y);
        dst[2 * j + 1] = __floats2half2_rn(v.z, v.w);
    }
}

// ---------------- host ----------------
extern "C" void kernel_launch(void* const* d_in, const int* in_sizes, int n_in,
                              void* d_out, int out_size)
{
    const float* x    = (const float*)d_in[0];
    const float* h    = (const float*)d_in[1];
    const float* Win  = (const float*)d_in[2];
    const float* Wh   = (const float*)d_in[3];
    const float* bias = (const float*)d_in[4];
    float* out = (float*)d_out;

    static int nsm = 0;
    if (nsm == 0) {
        cudaDeviceGetAttribute(&nsm, cudaDevAttrMultiProcessorCount, 0);
        if (nsm <= 0) nsm = 148;
        cudaFuncSetAttribute(gru_fused, cudaFuncAttributeMaxDynamicSharedMemorySize,
                             SMEM_ALLOC);
    }

    cvt_all_kernel<<<2048, 256>>>((const float4*)x, (const float4*)h,
                                  (const float4*)Win, (const float4*)Wh);
    gru_fused<<<nsm, THREADS, SMEM_ALLOC>>>(h, bias, out);
}

// round 14
// speedup vs baseline: 1.1755x; 1.1385x over previous
#include <cuda_runtime.h>
#include <cuda_fp16.h>
#include <math.h>
#include <stdint.h>

#define BATCH 8192
#define U2    2048
#define GL    6144

#define BM 128
#define BN 256
#define BK 64
#define STAGES 4
#define THREADS 512

#define A_STAGE_BYTES (BM * BK * 2)            // 16384: 128 rows x 128B, SW128
#define BROWB 528                               // B smem row bytes (512 data + 16 pad)
#define B_STAGE_BYTES (BK * BROWB)              // 33792
#define STAGE_BYTES (A_STAGE_BYTES + B_STAGE_BYTES)   // 50176
#define SMEM_ALLOC (STAGES * STAGE_BYTES + 256)

#define NT_A 1536      // A tiles: 64 m-blocks x 24 n-tiles (m-major)
#define NTOT 2048      // + 512 B tiles: 64 m-blocks x 8 n-tiles

// fp16 operand copies + intermediates (allocation-free scratch)
__device__ __half g_xH [(size_t)BATCH * U2];
__device__ __half g_hH [(size_t)BATCH * U2];
__device__ __half g_WinH[(size_t)U2 * GL];
__device__ __half g_WhH [(size_t)U2 * GL];
__device__ __half g_rhH[(size_t)BATCH * U2];   // fp16 r*h
__device__ float  g_U  [(size_t)BATCH * U2];   // update gate (fp32)
__device__ float  g_XH [(size_t)BATCH * U2];   // x@Win[:,2u:] (fp32)

// scheduling state (reset each launch inside cvt kernel)
__device__ unsigned g_work;
__device__ unsigned g_done[64];

// ---------------- helpers ----------------
__device__ __forceinline__ uint32_t smem_u32(const void* p) {
    uint32_t a;
    asm("{ .reg .u64 t; cvta.to.shared.u64 t, %1; cvt.u32.u64 %0, t; }" : "=r"(a) : "l"(p));
    return a;
}
__device__ __forceinline__ void cp16(uint32_t dst, const void* src) {
    asm volatile("cp.async.cg.shared.global [%0], [%1], 16;" :: "r"(dst), "l"(src));
}
__device__ __forceinline__ void cp_commit() {
    asm volatile("cp.async.commit_group;" ::: "memory");
}
template<int N> __device__ __forceinline__ void cp_wait() {
    asm volatile("cp.async.wait_group %0;" :: "n"(N) : "memory");
}
__device__ __forceinline__ void ldsm_x4(uint32_t* r, uint32_t addr) {
    asm volatile("ldmatrix.sync.aligned.m8n8.x4.shared.b16 {%0,%1,%2,%3}, [%4];"
                 : "=r"(r[0]), "=r"(r[1]), "=r"(r[2]), "=r"(r[3]) : "r"(addr));
}
__device__ __forceinline__ void ldsm_x4_t(uint32_t* r, uint32_t addr) {
    asm volatile("ldmatrix.sync.aligned.m8n8.x4.trans.shared.b16 {%0,%1,%2,%3}, [%4];"
                 : "=r"(r[0]), "=r"(r[1]), "=r"(r[2]), "=r"(r[3]) : "r"(addr));
}
__device__ __forceinline__ void mma_f16(float* d, const uint32_t* a, const uint32_t* b) {
    asm volatile(
        "mma.sync.aligned.m16n8k16.row.col.f32.f16.f16.f32 "
        "{%0,%1,%2,%3}, {%4,%5,%6,%7}, {%8,%9}, {%0,%1,%2,%3};"
        : "+f"(d[0]), "+f"(d[1]), "+f"(d[2]), "+f"(d[3])
        : "r"(a[0]), "r"(a[1]), "r"(a[2]), "r"(a[3]), "r"(b[0]), "r"(b[1]));
}
__device__ __forceinline__ unsigned ld_acq(const unsigned* p) {
    unsigned v;
    asm volatile("ld.acquire.gpu.b32 %0, [%1];" : "=r"(v) : "l"(p) : "memory");
    return v;
}
__device__ __forceinline__ float sigmoidf_(float x) { return 1.0f / (1.0f + __expf(-x)); }

// ---------------- tile decode ----------------
struct TileInfo {
    int mblk, n0, K, region;
    const __half *a0, *a1, *b0, *b1;
};
__device__ __forceinline__ TileInfo decode_tile(int t) {
    TileInfo ti;
    if (t < NT_A) {
        ti.mblk = t / 24;
        const int nt = t % 24;
        ti.n0 = nt * 256;
        ti.K  = (nt < 16) ? 4096 : 2048;
        ti.region = ti.n0 >> 11;                 // 0=r, 1=u, 2=xh
        ti.a0 = g_xH;  ti.a1 = g_hH;
        ti.b0 = g_WinH + ti.n0;  ti.b1 = g_WhH + ti.n0;
    } else {
        const int u = t - NT_A;
        ti.mblk = u >> 3;
        ti.n0 = (u & 7) * 256;
        ti.K = 2048; ti.region = 3;
        ti.a0 = g_rhH;  ti.a1 = g_rhH;
        ti.b0 = g_WhH + 4096 + ti.n0;  ti.b1 = ti.b0;
    }
    return ti;
}

// ---------------- stage fill (512 threads, BK=64) ----------------
__device__ __forceinline__ void fill_stage(int tid, uint32_t stA, uint32_t stB,
                                           int m0, int k0, const TileInfo& ti)
{
    // ---- A: row = tid>>2, 2 x 16B chunks each ----
    const int row = tid >> 2;
    const int c0a = (tid & 3) * 2;
#pragma unroll
    for (int j = 0; j < 2; j++) {
        const int ch = c0a + j;                  // 0..7
        const int kg = k0 + ch * 8;
        const __half* src = (kg < 2048)
            ? ti.a0 + (size_t)(m0 + row) * U2 + kg
            : ti.a1 + (size_t)(m0 + row) * U2 + (kg - 2048);
        cp16(stA + (uint32_t)(row << 7) + (uint32_t)(((ch ^ (row & 7)) << 4)), src);
    }
    // ---- B: k-row = tid>>3 (0..63), 4 x 16B chunks across 256 n ----
    const int kb = tid >> 3;
    const int kg = k0 + kb;
    const __half* brow = (kg < 2048)
        ? ti.b0 + (size_t)kg * GL
        : ti.b1 + (size_t)(kg - 2048) * GL;
    const uint32_t bbase = stB + (uint32_t)(kb * BROWB) + (uint32_t)((tid & 7) << 4);
#pragma unroll
    for (int q = 0; q < 4; q++)
        cp16(bbase + (uint32_t)(q << 7), brow + (tid & 7) * 8 + q * 64);
}

// ---------------- fused persistent GRU kernel ----------------
__global__ void __launch_bounds__(THREADS, 1)
gru_fused(const float* __restrict__ h_exact, const float* __restrict__ bias,
          float* __restrict__ out)
{
    extern __shared__ char smem_raw[];
    const uint32_t base = (smem_u32(smem_raw) + 127u) & ~127u;
    volatile int* sm_ints = (volatile int*)(smem_raw + STAGES * STAGE_BYTES + 128);

    const int tid  = threadIdx.x;
    const int lane = tid & 31;
    const int wid  = tid >> 5;
    const int warp_m = wid & 3;          // 32-row quarters
    const int warp_n = wid >> 2;         // 64-col quarters

    // ldmatrix lane decomposition
    const int g = lane >> 3;
    const int r = lane & 7;
    const int a_mlocal = ((g & 1) << 3) + r;
    const int a_khalf  = g >> 1;
    const uint32_t a_rowoff = (uint32_t)((warp_m * 32 + a_mlocal) << 7);
    const int b_klocal = ((g & 1) << 3) + r;
    const int b_noct   = g >> 1;

    // ---- initial tile grab + prologue ----
    if (tid == 0) sm_ints[0] = (int)atomicAdd(&g_work, 1u);
    __syncthreads();
    int t = sm_ints[0];
    TileInfo ti;
    if (t < NTOT) {
        ti = decode_tile(t);
        if (ti.region == 3) {
            if (tid == 0) {
                while (ld_acq(&g_done[ti.mblk]) < 24u) __nanosleep(64);
            }
            __syncthreads();
        }
        fill_stage(tid, base, base + A_STAGE_BYTES, ti.mblk * 128, 0, ti);
        cp_commit();
        fill_stage(tid, base + STAGE_BYTES, base + STAGE_BYTES + A_STAGE_BYTES,
                   ti.mblk * 128, BK, ti);
        cp_commit();
    }

    while (t < NTOT) {
        const int m0 = ti.mblk * 128;
        const int NC = ti.K / BK;        // 64 or 32 (multiple of 4)

        float d[2][8][4];
#pragma unroll
        for (int mf = 0; mf < 2; mf++)
#pragma unroll
            for (int nf = 0; nf < 8; nf++)
#pragma unroll
                for (int q = 0; q < 4; q++) d[mf][nf][q] = 0.0f;

        // ---- main K loop (R8-identical: fill BEFORE wait+barrier) ----
        for (int c = 0; c < NC; c++) {
            if (c + 2 < NC) {
                const uint32_t sb = base + (uint32_t)((c + 2) % STAGES) * STAGE_BYTES;
                fill_stage(tid, sb, sb + A_STAGE_BYTES, m0, (c + 2) * BK, ti);
            }
            cp_commit();
            cp_wait<2>();
            __syncthreads();

            const uint32_t cs  = base + (uint32_t)(c % STAGES) * STAGE_BYTES;
            const uint32_t stB = cs + A_STAGE_BYTES;

#pragma unroll
            for (int ks = 0; ks < 4; ks++) {
                uint32_t a[2][4];
#pragma unroll
                for (int mf = 0; mf < 2; mf++) {
                    const uint32_t addr = cs + a_rowoff + (uint32_t)(mf << 11)
                                        + (uint32_t)((((ks << 1) + a_khalf) ^ r) << 4);
                    ldsm_x4(a[mf], addr);
                }
                uint32_t b[8][2];
#pragma unroll
                for (int pr = 0; pr < 4; pr++) {
                    uint32_t bb[4];
                    const uint32_t addr = stB
                        + (uint32_t)((ks * 16 + b_klocal) * BROWB)
                        + (uint32_t)((warp_n * 64 + pr * 16 + b_noct * 8) << 1);
                    ldsm_x4_t(bb, addr);
                    b[pr * 2 + 0][0] = bb[0]; b[pr * 2 + 0][1] = bb[1];
                    b[pr * 2 + 1][0] = bb[2]; b[pr * 2 + 1][1] = bb[3];
                }
#pragma unroll
                for (int mf = 0; mf < 2; mf++)
#pragma unroll
                    for (int nf = 0; nf < 8; nf++)
                        mma_f16(d[mf][nf], a[mf], b[nf]);
            }
        }
        cp_wait<0>();

        // ---- grab + prefill next tile (per-tile, outside inner loop) ----
        __syncthreads();                 // all stage readers retired
        if (tid == 0) {
            const int tn = (int)atomicAdd(&g_work, 1u);
            int rdy = 1;
            if (tn >= NT_A && tn < NTOT) {
                const int mb = (tn - NT_A) >> 3;
                if (ld_acq(&g_done[mb]) < 24u) rdy = 0;
            }
            sm_ints[1] = tn;
            sm_ints[2] = rdy;
        }
        __syncthreads();                 // broadcast tn, rdy
        const int t_next = sm_ints[1];
        const int ready_next = sm_ints[2];
        TileInfo tiN;
        if (t_next < NTOT) {
            tiN = decode_tile(t_next);
            if (ready_next) {
                // stages 0/1 free: last readers were chunks NC-4/NC-3
                fill_stage(tid, base, base + A_STAGE_BYTES, tiN.mblk * 128, 0, tiN);
                cp_commit();
                fill_stage(tid, base + STAGE_BYTES,
                           base + STAGE_BYTES + A_STAGE_BYTES,
                           tiN.mblk * 128, BK, tiN);
                cp_commit();
            }
        }

        // ---- epilogue (overlaps next tile's in-flight fills) ----
        const int region = ti.region;
        const int n0 = ti.n0;
#pragma unroll
        for (int mf = 0; mf < 2; mf++) {
#pragma unroll
            for (int nf = 0; nf < 8; nf++) {
                const int gc = n0 + warp_n * 64 + nf * 8 + (lane & 3) * 2;
#pragma unroll
                for (int half = 0; half < 2; half++) {
                    const int grow = m0 + warp_m * 32 + mf * 16 + (lane >> 2) + half * 8;
                    const float v0 = d[mf][nf][half * 2 + 0];
                    const float v1 = d[mf][nf][half * 2 + 1];
                    const size_t rb = (size_t)grow * U2;

                    if (region == 0) {
                        const int nl = gc;
                        float2 bv = *(const float2*)(bias + gc);
                        float2 hv = *(const float2*)(h_exact + rb + nl);
                        __half2 o = __floats2half2_rn(sigmoidf_(v0 + bv.x) * hv.x,
                                                      sigmoidf_(v1 + bv.y) * hv.y);
                        *(__half2*)(g_rhH + rb + nl) = o;
                    } else if (region == 1) {
                        const int nl = gc & 2047;
                        float2 bv = *(const float2*)(bias + gc);
                        float2 o;
                        o.x = sigmoidf_(v0 + bv.x);
                        o.y = sigmoidf_(v1 + bv.y);
                        *(float2*)(g_U + rb + nl) = o;
                    } else if (region == 2) {
                        const int nl = gc & 2047;
                        float2 o; o.x = v0; o.y = v1;
                        *(float2*)(g_XH + rb + nl) = o;
                    } else {
                        float2 xh = *(const float2*)(g_XH + rb + gc);
                        float2 uu = *(const float2*)(g_U  + rb + gc);
                        float2 hv = *(const float2*)(h_exact + rb + gc);
                        float2 bv = *(const float2*)(bias + 4096 + gc);
                        float2 o;
                        const float c0 = tanhf(v0 + xh.x + bv.x);
                        const float c1 = tanhf(v1 + xh.y + bv.y);
                        o.x = uu.x * hv.x + (1.0f - uu.x) * c0;
                        o.y = uu.y * hv.y + (1.0f - uu.y) * c1;
                        *(float2*)(out + rb + gc) = o;
                    }
                }
            }
        }

        // ---- publish completion (A tiles), then advance ----
        __threadfence();
        __syncthreads();                 // protects sm_ints reuse as well
        if (region < 3 && tid == 0) atomicAdd(&g_done[ti.mblk], 1u);

        t = t_next;
        if (t >= NTOT) break;
        ti = tiN;
        if (!ready_next) {
            // dependency wasn't met at prefill time: poll now (own
            // contribution already published above -> no self-deadlock)
            if (tid == 0) {
                while (ld_acq(&g_done[ti.mblk]) < 24u) __nanosleep(64);
            }
            __syncthreads();
            fill_stage(tid, base, base + A_STAGE_BYTES, ti.mblk * 128, 0, ti);
            cp_commit();
            fill_stage(tid, base + STAGE_BYTES, base + STAGE_BYTES + A_STAGE_BYTES,
                       ti.mblk * 128, BK, ti);
            cp_commit();
        }
    }
}

// ---------------- fused fp32 -> fp16 conversion + counter reset ----------------
__global__ void __launch_bounds__(256)
cvt_all_kernel(const float4* __restrict__ x, const float4* __restrict__ h,
               const float4* __restrict__ wi, const float4* __restrict__ wh)
{
    if (blockIdx.x == 0) {
        if (threadIdx.x < 64) g_done[threadIdx.x] = 0u;
        if (threadIdx.x == 64) g_work = 0u;
    }
    const int nx = BATCH * U2 / 4;
    const int nw = U2 * GL / 4;
    const int total = 2 * nx + 2 * nw;
    for (int i = blockIdx.x * blockDim.x + threadIdx.x; i < total;
         i += gridDim.x * blockDim.x) {
        const float4* src; __half2* dst; int j;
        if (i < nx)               { src = x;  dst = (__half2*)g_xH;   j = i; }
        else if (i < 2 * nx)      { src = h;  dst = (__half2*)g_hH;   j = i - nx; }
        else if (i < 2 * nx + nw) { src = wi; dst = (__half2*)g_WinH; j = i - 2 * nx; }
        else                      { src = wh; dst = (__half2*)g_WhH;  j = i - 2 * nx - nw; }
        float4 v = src[j];
        dst[2 * j + 0] = __floats2half2_rn(v.x, v.y);
        dst[2 * j + 1] = __floats2half2_rn(v.z, v.w);
    }
}

// ---------------- host ----------------
extern "C" void kernel_launch(void* const* d_in, const int* in_sizes, int n_in,
                              void* d_out, int out_size)
{
    const float* x    = (const float*)d_in[0];
    const float* h    = (const float*)d_in[1];
    const float* Win  = (const float*)d_in[2];
    const float* Wh   = (const float*)d_in[3];
    const float* bias = (const float*)d_in[4];
    float* out = (float*)d_out;

    static int nsm = 0;
    if (nsm == 0) {
        cudaDeviceGetAttribute(&nsm, cudaDevAttrMultiProcessorCount, 0);
        if (nsm <= 0) nsm = 148;
        cudaFuncSetAttribute(gru_fused, cudaFuncAttributeMaxDynamicSharedMemorySize,
                             SMEM_ALLOC);
    }

    cvt_all_kernel<<<4096, 256>>>((const float4*)x, (const float4*)h,
                                  (const float4*)Win, (const float4*)Wh);
    gru_fused<<<nsm, THREADS, SMEM_ALLOC>>>(h, bias, out);
}

// round 16
// speedup vs baseline: 1.2099x; 1.0293x over previous
#include <cuda_runtime.h>
#include <cuda_fp16.h>
#include <math.h>
#include <stdint.h>

#define BATCH 8192
#define U2    2048
#define GL    6144

#define BM 128
#define BN 256
#define BK 64
#define STAGES 4
#define THREADS 512

#define A_STAGE_BYTES (BM * BK * 2)            // 16384: 128 rows x 128B, SW128
#define BROWB 528                               // B smem row bytes (512 data + 16 pad)
#define B_STAGE_BYTES (BK * BROWB)              // 33792
#define STAGE_BYTES (A_STAGE_BYTES + B_STAGE_BYTES)   // 50176
#define SMEM_ALLOC (STAGES * STAGE_BYTES + 256)

#define NT_A 1536      // A tiles: 64 m-blocks x 24 n-tiles (m-major)
#define NTOT 2048      // + 512 B tiles: 64 m-blocks x 8 n-tiles

// fp16 operand copies + intermediates (allocation-free scratch)
__device__ __half g_xH [(size_t)BATCH * U2];
__device__ __half g_hH [(size_t)BATCH * U2];
__device__ __half g_WinH[(size_t)U2 * GL];
__device__ __half g_WhH [(size_t)U2 * GL];
__device__ __half g_rhH[(size_t)BATCH * U2];   // fp16 r*h
__device__ float  g_U  [(size_t)BATCH * U2];   // update gate (fp32)
__device__ float  g_XH [(size_t)BATCH * U2];   // x@Win[:,2u:] (fp32)

// scheduling state (reset each launch inside cvt kernel)
__device__ unsigned g_work;
__device__ unsigned g_done[64];

// ---------------- helpers ----------------
__device__ __forceinline__ uint32_t smem_u32(const void* p) {
    uint32_t a;
    asm("{ .reg .u64 t; cvta.to.shared.u64 t, %1; cvt.u32.u64 %0, t; }" : "=r"(a) : "l"(p));
    return a;
}
__device__ __forceinline__ void cp16(uint32_t dst, const void* src) {
    asm volatile("cp.async.cg.shared.global [%0], [%1], 16;" :: "r"(dst), "l"(src));
}
__device__ __forceinline__ void cp_commit() {
    asm volatile("cp.async.commit_group;" ::: "memory");
}
template<int N> __device__ __forceinline__ void cp_wait() {
    asm volatile("cp.async.wait_group %0;" :: "n"(N) : "memory");
}
__device__ __forceinline__ void ldsm_x4(uint32_t* r, uint32_t addr) {
    asm volatile("ldmatrix.sync.aligned.m8n8.x4.shared.b16 {%0,%1,%2,%3}, [%4];"
                 : "=r"(r[0]), "=r"(r[1]), "=r"(r[2]), "=r"(r[3]) : "r"(addr));
}
__device__ __forceinline__ void ldsm_x4_t(uint32_t* r, uint32_t addr) {
    asm volatile("ldmatrix.sync.aligned.m8n8.x4.trans.shared.b16 {%0,%1,%2,%3}, [%4];"
                 : "=r"(r[0]), "=r"(r[1]), "=r"(r[2]), "=r"(r[3]) : "r"(addr));
}
__device__ __forceinline__ void mma_f16(float* d, const uint32_t* a, const uint32_t* b) {
    asm volatile(
        "mma.sync.aligned.m16n8k16.row.col.f32.f16.f16.f32 "
        "{%0,%1,%2,%3}, {%4,%5,%6,%7}, {%8,%9}, {%0,%1,%2,%3};"
        : "+f"(d[0]), "+f"(d[1]), "+f"(d[2]), "+f"(d[3])
        : "r"(a[0]), "r"(a[1]), "r"(a[2]), "r"(a[3]), "r"(b[0]), "r"(b[1]));
}
__device__ __forceinline__ unsigned ld_acq(const unsigned* p) {
    unsigned v;
    asm volatile("ld.acquire.gpu.b32 %0, [%1];" : "=r"(v) : "l"(p) : "memory");
    return v;
}
__device__ __forceinline__ float sigmoidf_(float x) { return 1.0f / (1.0f + __expf(-x)); }

// ---------------- tile decode ----------------
struct TileInfo {
    int mblk, n0, K, region;
    const __half *a0, *a1, *b0, *b1;
};
__device__ __forceinline__ TileInfo decode_tile(int t) {
    TileInfo ti;
    if (t < NT_A) {
        ti.mblk = t / 24;
        const int nt = t % 24;
        ti.n0 = nt * 256;
        ti.K  = (nt < 16) ? 4096 : 2048;
        ti.region = ti.n0 >> 11;                 // 0=r, 1=u, 2=xh
        ti.a0 = g_xH;  ti.a1 = g_hH;
        ti.b0 = g_WinH + ti.n0;  ti.b1 = g_WhH + ti.n0;
    } else {
        const int u = t - NT_A;
        ti.mblk = u >> 3;
        ti.n0 = (u & 7) * 256;
        ti.K = 2048; ti.region = 3;
        ti.a0 = g_rhH;  ti.a1 = g_rhH;
        ti.b0 = g_WhH + 4096 + ti.n0;  ti.b1 = ti.b0;
    }
    return ti;
}

// ---------------- stage fill (512 threads, BK=64) ----------------
__device__ __forceinline__ void fill_stage(int tid, uint32_t stA, uint32_t stB,
                                           int m0, int k0, const TileInfo& ti)
{
    // ---- A: row = tid>>2, 2 x 16B chunks each ----
    const int row = tid >> 2;
    const int c0a = (tid & 3) * 2;
#pragma unroll
    for (int j = 0; j < 2; j++) {
        const int ch = c0a + j;                  // 0..7
        const int kg = k0 + ch * 8;
        const __half* src = (kg < 2048)
            ? ti.a0 + (size_t)(m0 + row) * U2 + kg
            : ti.a1 + (size_t)(m0 + row) * U2 + (kg - 2048);
        cp16(stA + (uint32_t)(row << 7) + (uint32_t)(((ch ^ (row & 7)) << 4)), src);
    }
    // ---- B: k-row = tid>>3 (0..63), 4 x 16B chunks across 256 n ----
    const int kb = tid >> 3;
    const int kg = k0 + kb;
    const __half* brow = (kg < 2048)
        ? ti.b0 + (size_t)kg * GL
        : ti.b1 + (size_t)(kg - 2048) * GL;
    const uint32_t bbase = stB + (uint32_t)(kb * BROWB) + (uint32_t)((tid & 7) << 4);
#pragma unroll
    for (int q = 0; q < 4; q++)
        cp16(bbase + (uint32_t)(q << 7), brow + (tid & 7) * 8 + q * 64);
}

// ---------------- fused persistent GRU kernel (R8 configuration) ----------------
__global__ void __launch_bounds__(THREADS, 1)
gru_fused(const float* __restrict__ h_exact, const float* __restrict__ bias,
          float* __restrict__ out)
{
    extern __shared__ char smem_raw[];
    const uint32_t base = (smem_u32(smem_raw) + 127u) & ~127u;
    volatile int* sm_bcast = (volatile int*)(smem_raw + STAGES * STAGE_BYTES + 128);

    const int tid  = threadIdx.x;
    const int lane = tid & 31;
    const int wid  = tid >> 5;
    const int warp_m = wid & 3;          // 32-row quarters
    const int warp_n = wid >> 2;         // 64-col quarters

    // ldmatrix lane decomposition
    const int g = lane >> 3;
    const int r = lane & 7;
    const int a_mlocal = ((g & 1) << 3) + r;
    const int a_khalf  = g >> 1;
    const uint32_t a_rowoff = (uint32_t)((warp_m * 32 + a_mlocal) << 7);
    const int b_klocal = ((g & 1) << 3) + r;
    const int b_noct   = g >> 1;

    for (;;) {
        // ---- grab a tile ----
        if (tid == 0) *sm_bcast = (int)atomicAdd(&g_work, 1u);
        __syncthreads();
        const int t = *sm_bcast;
        if (t >= NTOT) break;

        const TileInfo ti = decode_tile(t);
        if (ti.region == 3) {
            if (tid == 0) {
                while (ld_acq(&g_done[ti.mblk]) < 24u) __nanosleep(128);
            }
            __syncthreads();
            __threadfence();
        }
        const int m0 = ti.mblk * 128;
        const int NC = ti.K / BK;

        float d[2][8][4];
#pragma unroll
        for (int mf = 0; mf < 2; mf++)
#pragma unroll
            for (int nf = 0; nf < 8; nf++)
#pragma unroll
                for (int q = 0; q < 4; q++) d[mf][nf][q] = 0.0f;

        // ---- pipeline prologue ----
        fill_stage(tid, base, base + A_STAGE_BYTES, m0, 0, ti);
        cp_commit();
        fill_stage(tid, base + STAGE_BYTES, base + STAGE_BYTES + A_STAGE_BYTES,
                   m0, BK, ti);
        cp_commit();

        // ---- main K loop (R8: fill BEFORE wait+barrier, 4 stages, wait<2>) ----
        for (int c = 0; c < NC; c++) {
            if (c + 2 < NC) {
                const uint32_t sb = base + (uint32_t)((c + 2) % STAGES) * STAGE_BYTES;
                fill_stage(tid, sb, sb + A_STAGE_BYTES, m0, (c + 2) * BK, ti);
            }
            cp_commit();
            cp_wait<2>();
            __syncthreads();

            const uint32_t cs  = base + (uint32_t)(c % STAGES) * STAGE_BYTES;
            const uint32_t stB = cs + A_STAGE_BYTES;

#pragma unroll
            for (int ks = 0; ks < 4; ks++) {
                uint32_t a[2][4];
#pragma unroll
                for (int mf = 0; mf < 2; mf++) {
                    const uint32_t addr = cs + a_rowoff + (uint32_t)(mf << 11)
                                        + (uint32_t)((((ks << 1) + a_khalf) ^ r) << 4);
                    ldsm_x4(a[mf], addr);
                }
                uint32_t b[8][2];
#pragma unroll
                for (int pr = 0; pr < 4; pr++) {
                    uint32_t bb[4];
                    const uint32_t addr = stB
                        + (uint32_t)((ks * 16 + b_klocal) * BROWB)
                        + (uint32_t)((warp_n * 64 + pr * 16 + b_noct * 8) << 1);
                    ldsm_x4_t(bb, addr);
                    b[pr * 2 + 0][0] = bb[0]; b[pr * 2 + 0][1] = bb[1];
                    b[pr * 2 + 1][0] = bb[2]; b[pr * 2 + 1][1] = bb[3];
                }
#pragma unroll
                for (int mf = 0; mf < 2; mf++)
#pragma unroll
                    for (int nf = 0; nf < 8; nf++)
                        mma_f16(d[mf][nf], a[mf], b[nf]);
            }
        }
        cp_wait<0>();

        // ---- epilogue ----
        const int region = ti.region;
        const int n0 = ti.n0;
#pragma unroll
        for (int mf = 0; mf < 2; mf++) {
#pragma unroll
            for (int nf = 0; nf < 8; nf++) {
                const int gc = n0 + warp_n * 64 + nf * 8 + (lane & 3) * 2;
#pragma unroll
                for (int half = 0; half < 2; half++) {
                    const int grow = m0 + warp_m * 32 + mf * 16 + (lane >> 2) + half * 8;
                    const float v0 = d[mf][nf][half * 2 + 0];
                    const float v1 = d[mf][nf][half * 2 + 1];
                    const size_t rb = (size_t)grow * U2;

                    if (region == 0) {
                        const int nl = gc;
                        float2 bv = *(const float2*)(bias + gc);
                        float2 hv = *(const float2*)(h_exact + rb + nl);
                        __half2 o = __floats2half2_rn(sigmoidf_(v0 + bv.x) * hv.x,
                                                      sigmoidf_(v1 + bv.y) * hv.y);
                        *(__half2*)(g_rhH + rb + nl) = o;
                    } else if (region == 1) {
                        const int nl = gc & 2047;
                        float2 bv = *(const float2*)(bias + gc);
                        float2 o;
                        o.x = sigmoidf_(v0 + bv.x);
                        o.y = sigmoidf_(v1 + bv.y);
                        *(float2*)(g_U + rb + nl) = o;
                    } else if (region == 2) {
                        const int nl = gc & 2047;
                        float2 o; o.x = v0; o.y = v1;
                        *(float2*)(g_XH + rb + nl) = o;
                    } else {
                        float2 xh = *(const float2*)(g_XH + rb + gc);
                        float2 uu = *(const float2*)(g_U  + rb + gc);
                        float2 hv = *(const float2*)(h_exact + rb + gc);
                        float2 bv = *(const float2*)(bias + 4096 + gc);
                        float2 o;
                        const float c0 = tanhf(v0 + xh.x + bv.x);
                        const float c1 = tanhf(v1 + xh.y + bv.y);
                        o.x = uu.x * hv.x + (1.0f - uu.x) * c0;
                        o.y = uu.y * hv.y + (1.0f - uu.y) * c1;
                        *(float2*)(out + rb + gc) = o;
                    }
                }
            }
        }

        // ---- publish completion (A tiles) ----
        __threadfence();
        __syncthreads();                 // also protects sm_bcast reuse
        if (region < 3 && tid == 0) atomicAdd(&g_done[ti.mblk], 1u);
    }
}

// ---------------- fused fp32 -> fp16 conversion + counter reset ----------------
__global__ void __launch_bounds__(256)
cvt_all_kernel(const float4* __restrict__ x, const float4* __restrict__ h,
               const float4* __restrict__ wi, const float4* __restrict__ wh)
{
    if (blockIdx.x == 0) {
        if (threadIdx.x < 64) g_done[threadIdx.x] = 0u;
        if (threadIdx.x == 64) g_work = 0u;
    }
    const int nx = BATCH * U2 / 4;
    const int nw = U2 * GL / 4;
    const int total = 2 * nx + 2 * nw;
    for (int i = blockIdx.x * blockDim.x + threadIdx.x; i < total;
         i += gridDim.x * blockDim.x) {
        const float4* src; __half2* dst; int j;
        if (i < nx)               { src = x;  dst = (__half2*)g_xH;   j = i; }
        else if (i < 2 * nx)      { src = h;  dst = (__half2*)g_hH;   j = i - nx; }
        else if (i < 2 * nx + nw) { src = wi; dst = (__half2*)g_WinH; j = i - 2 * nx; }
        else                      { src = wh; dst = (__half2*)g_WhH;  j = i - 2 * nx - nw; }
        float4 v = src[j];
        dst[2 * j + 0] = __floats2half2_rn(v.x, v.y);
        dst[2 * j + 1] = __floats2half2_rn(v.z, v.w);
    }
}

// ---------------- host ----------------
extern "C" void kernel_launch(void* const* d_in, const int* in_sizes, int n_in,
                              void* d_out, int out_size)
{
    const float* x    = (const float*)d_in[0];
    const float* h    = (const float*)d_in[1];
    const float* Win  = (const float*)d_in[2];
    const float* Wh   = (const float*)d_in[3];
    const float* bias = (const float*)d_in[4];
    float* out = (float*)d_out;

    static int nsm = 0;
    if (nsm == 0) {
        cudaDeviceGetAttribute(&nsm, cudaDevAttrMultiProcessorCount, 0);
        if (nsm <= 0) nsm = 148;
        cudaFuncSetAttribute(gru_fused, cudaFuncAttributeMaxDynamicSharedMemorySize,
                             SMEM_ALLOC);
    }

    cvt_all_kernel<<<4096, 256>>>((const float4*)x, (const float4*)h,
                                  (const float4*)Win, (const float4*)Wh);
    gru_fused<<<nsm, THREADS, SMEM_ALLOC>>>(h, bias, out);
}